// round 17
// baseline (speedup 1.0000x reference)
#include <cuda_runtime.h>
#include <cuda_fp16.h>
#include <cstdint>

#define NN  100000
#define EIN 1600000
#define ECN 800000
#define GN  2000
#define FDIM 512
#define CC  128

// -------- scratch (device globals; no allocation) --------
__device__ __half g_xw[NN*CC];
__device__ __half g_f[NN*CC];
__device__ float g_z[NN*CC];
__device__ float g_el[NN*4];
__device__ float g_er[NN*4];
__device__ float g_iso[NN];
__device__ float g_isi[NN];
__device__ float g_att[NN];
__device__ float g_gsum[GN*CC];
__device__ float g_gcnt[GN];
__device__ float g_bnsum[2*CC];
__device__ float g_bnsq[2*CC];
__device__ __half g_wp[256*FDIM];
__device__ float g_cvec[256];
// CSR scratch
__device__ int g_idegi[NN];
__device__ int g_idegc[NN];
__device__ int g_rpi[NN];
__device__ int g_rpc[NN];
__device__ int g_curi[NN];
__device__ int g_curc[NN];
__device__ int g_bsum[1024];
__device__ int g_ci[EIN];
__device__ int g_ccol[ECN];

__device__ __forceinline__ float leakyr(float x) { return x >= 0.f ? x : 0.2f * x; }

__device__ __forceinline__ void mma_f16(float* d, const uint32_t* a, const uint32_t* b) {
    asm volatile(
        "mma.sync.aligned.m16n8k16.row.col.f32.f16.f16.f32 "
        "{%0,%1,%2,%3}, {%4,%5,%6,%7}, {%8,%9}, {%0,%1,%2,%3};"
        : "+f"(d[0]), "+f"(d[1]), "+f"(d[2]), "+f"(d[3])
        : "r"(a[0]), "r"(a[1]), "r"(a[2]), "r"(a[3]), "r"(b[0]), "r"(b[1]));
}

__device__ __forceinline__ uint32_t packh2(float lo, float hi) {
    __half2 h = __floats2half2_rn(lo, hi);
    return *(uint32_t*)&h;
}

__device__ __forceinline__ void cp16(uint32_t dst, const void* src, int sz) {
    asm volatile("cp.async.cg.shared.global [%0], [%1], 16, %2;"
                 :: "r"(dst), "l"(src), "r"(sz) : "memory");
}

// -------- degrees + graph-count in one pass --------
__global__ void edge_deg(const int* __restrict__ isrc, const int* __restrict__ idst,
                         const int* __restrict__ cdst, const int* __restrict__ gid,
                         float* iso, int* idegi, int* idegc, float* gcnt) {
    int t = blockIdx.x * blockDim.x + threadIdx.x;
    if (t < EIN) {
        atomicAdd(&iso[isrc[t]], 1.f);
        atomicAdd(&idegi[idst[t]], 1);
    } else if (t < EIN + ECN) {
        atomicAdd(&idegc[cdst[t - EIN]], 1);
    } else if (t < EIN + ECN + NN) {
        atomicAdd(&gcnt[gid[t - EIN - ECN]], 1.f);
    }
}

// -------- dual scan stage 1 (+ inv-sqrt degree finalize) --------
__global__ void scan1dual(const int* __restrict__ in1, const int* __restrict__ in2,
                          int* out1, int* out2, int* bsum,
                          float* iso, float* isi, int n) {
    __shared__ int sh1[256], sh2[256];
    int i = blockIdx.x * 256 + threadIdx.x;
    int v1 = (i < n) ? in1[i] : 0;
    int v2 = (i < n) ? in2[i] : 0;
    if (i < n) {
        isi[i] = rsqrtf(fmaxf((float)v1, 1.f));
        iso[i] = rsqrtf(fmaxf(iso[i], 1.f));
    }
    sh1[threadIdx.x] = v1; sh2[threadIdx.x] = v2;
    __syncthreads();
    for (int off = 1; off < 256; off <<= 1) {
        int t1 = (threadIdx.x >= off) ? sh1[threadIdx.x - off] : 0;
        int t2 = (threadIdx.x >= off) ? sh2[threadIdx.x - off] : 0;
        __syncthreads();
        sh1[threadIdx.x] += t1; sh2[threadIdx.x] += t2;
        __syncthreads();
    }
    if (i < n) { out1[i] = sh1[threadIdx.x] - v1; out2[i] = sh2[threadIdx.x] - v2; }
    if (threadIdx.x == 255) {
        bsum[blockIdx.x] = sh1[255];
        bsum[512 + blockIdx.x] = sh2[255];
    }
}

// -------- fused scan stages 2+3: each block derives its own prefix --------
__global__ void scan23dual(int* out1, int* out2, const int* __restrict__ bsum,
                           int* cur1, int* cur2, int n, int nb) {
    __shared__ int sh1[256], sh2[256];
    int t = threadIdx.x;
    int b = blockIdx.x;
    // partial sums of bsum[0..b)
    int p1 = 0, p2 = 0;
    for (int k = t; k < b; k += 256) {
        p1 += __ldg(bsum + k);
        p2 += __ldg(bsum + 512 + k);
    }
    sh1[t] = p1; sh2[t] = p2;
    __syncthreads();
    for (int off = 128; off; off >>= 1) {
        if (t < off) { sh1[t] += sh1[t + off]; sh2[t] += sh2[t + off]; }
        __syncthreads();
    }
    int base1 = sh1[0], base2 = sh2[0];
    int i = b * 256 + t;
    if (i < n) {
        int r1 = out1[i] + base1;
        int r2 = out2[i] + base2;
        out1[i] = r1; out2[i] = r2;
        cur1[i] = r1; cur2[i] = r2;
    }
}
__global__ void scatter_dual(const int* __restrict__ isrc, const int* __restrict__ idst,
                             const int* __restrict__ csrc, const int* __restrict__ cdst,
                             int* curi, int* curc, int* ci, int* ccol) {
    int t = blockIdx.x * blockDim.x + threadIdx.x;
    if (t < EIN) {
        int p = atomicAdd(&curi[idst[t]], 1);
        ci[p] = isrc[t];
    } else if (t < EIN + ECN) {
        int e = t - EIN;
        int p = atomicAdd(&curc[cdst[e]], 1);
        ccol[p] = csrc[e];
    }
}

// ===================================================================
// prep_all: weight fold + bias fold + zero el/er/bn (+ one-time init)
// ===================================================================
__global__ __launch_bounds__(256) void prep_all(
    const float* __restrict__ Wgc, const float* __restrict__ Wgat,
    const float* __restrict__ gamP, const float* __restrict__ betP,
    const float* __restrict__ bnsumP, const float* __restrict__ bnsqP, int hasAff,
    int K, __half* __restrict__ Wp, float* __restrict__ cvec,
    float* __restrict__ el, float* __restrict__ er,
    float* __restrict__ bnsumC, float* __restrict__ bnsqC,
    int initAll, float* iso, int* idegi, int* idegc, float* att,
    float* gsum, float* gcnt)
{
    int b = blockIdx.x;
    int t = threadIdx.x;
    if (b < K) {
        int k = b, j = t;
        float sc = 1.f;
        if (hasAff) {
            float mu = bnsumP[k] / (float)NN;
            float var = bnsqP[k] / (float)NN - mu * mu;
            sc = gamP[k] * rsqrtf(var + 1e-5f);
        }
        float w = (j < 128) ? Wgc[k * 128 + j] : Wgat[k * 128 + j - 128];
        Wp[(size_t)j * K + k] = __float2half(sc * w);
        return;
    }
    b -= K;
    if (b < 256) {
        __shared__ float sh[256];
        int j = b;
        float acc = 0.f;
        if (hasAff) {
            const float* W = (j < 128) ? (Wgc + j) : (Wgat + j - 128);
            for (int k = t; k < K; k += 256) {
                float mu = bnsumP[k] / (float)NN;
                float var = bnsqP[k] / (float)NN - mu * mu;
                float sck = gamP[k] * rsqrtf(var + 1e-5f);
                float shk = betP[k] - mu * sck;
                acc += shk * W[(size_t)k * 128];
            }
        }
        sh[t] = acc;
        __syncthreads();
        for (int off = 128; off; off >>= 1) {
            if (t < off) sh[t] += sh[t + off];
            __syncthreads();
        }
        if (t == 0) cvec[j] = sh[0];
        return;
    }
    b -= 256;
    int idx = b * 256 + t;
    if (idx < NN * 4) { el[idx] = 0.f; er[idx] = 0.f; }
    if (idx < CC) { bnsumC[idx] = 0.f; bnsqC[idx] = 0.f; }
    if (initAll) {
        if (idx < NN) { iso[idx] = 0.f; idegi[idx] = 0; idegc[idx] = 0; att[idx] = 0.f; }
        if (idx < GN * CC) gsum[idx] = 0.f;
        if (idx < GN) gcnt[idx] = 0.f;
    }
}

// ===================================================================
// Persistent dual-GEMM, fp16 m16n8k16 mma, cp.async 3-stage, BK=16
// el/er: plain store for H=4 (unique writer), atomic for H=1
// ===================================================================
__global__ __launch_bounds__(512, 1) void gemm_dual_async(
    const float* __restrict__ A, const __half* __restrict__ Wp,
    const float* __restrict__ cvec,
    __half* __restrict__ Ca, __half* __restrict__ Cb,
    const float* __restrict__ rowscale,
    const float* __restrict__ alv, const float* __restrict__ arv,
    float* __restrict__ el, float* __restrict__ er,
    int M, int K, int H, int ntiles)
{
    __shared__ __align__(16) float As[3][128 * 16];
    __shared__ __align__(16) __half Bs[3][256 * 16];

    const int tid = threadIdx.x;
    const int lane = tid & 31;
    const int wid = tid >> 5;
    const int wm = wid & 3;
    const int wn = wid >> 2;
    const int iters = K >> 4;

    const int ar_ = tid >> 2, akg = tid & 3;
    const int a_soff = ar_ * 16 + ((akg * 4) ^ (4 * (ar_ & 3)));
    const int bn = tid >> 1, bg = tid & 1;
    const int b_soff = bn * 16 + ((bg ^ (bn & 1)) << 3);
    const __half* b_src_base = Wp + (size_t)bn * K + bg * 8;

    for (int tile = blockIdx.x; tile < ntiles; tile += gridDim.x) {
        const int row0 = tile * 128;
        const int a_sz = (row0 + ar_ < M) ? 16 : 0;
        const float* a_src_base = A + (size_t)(row0 + ar_) * K + akg * 4;

        float acc[2][8][4];
#pragma unroll
        for (int i = 0; i < 2; i++)
#pragma unroll
            for (int j = 0; j < 8; j++)
#pragma unroll
                for (int q = 0; q < 4; q++) acc[i][j][q] = 0.f;

        asm volatile("cp.async.wait_group 0;" ::: "memory");
        __syncthreads();

        auto loadTile = [&](int it) {
            int buf = it % 3;
            int k0 = it * 16;
            cp16((uint32_t)__cvta_generic_to_shared(&As[buf][a_soff]), a_src_base + k0, a_sz);
            cp16((uint32_t)__cvta_generic_to_shared(&Bs[buf][b_soff]), b_src_base + k0, 16);
            asm volatile("cp.async.commit_group;" ::: "memory");
        };

        loadTile(0);
        if (iters > 1) loadTile(1);
        else asm volatile("cp.async.commit_group;" ::: "memory");

        for (int it = 0; it < iters; ++it) {
            asm volatile("cp.async.wait_group 1;" ::: "memory");
            __syncthreads();
            if (it + 2 < iters) loadTile(it + 2);
            else asm volatile("cp.async.commit_group;" ::: "memory");

            const float* as = As[it % 3];
            const __half* bs = Bs[it % 3];

            uint32_t afr[2][4], bfr[8][2];
            const int c = (lane & 3) * 2;
#pragma unroll
            for (int i = 0; i < 2; i++) {
                int r = wm * 32 + i * 16 + (lane >> 2);
                int r2 = r + 8;
                int sw = 4 * (r & 3);
                int sw2 = 4 * (r2 & 3);
                float2 f00 = *(const float2*)&as[r * 16 + (c ^ sw)];
                float2 f10 = *(const float2*)&as[r2 * 16 + (c ^ sw2)];
                float2 f01 = *(const float2*)&as[r * 16 + ((c + 8) ^ sw)];
                float2 f11 = *(const float2*)&as[r2 * 16 + ((c + 8) ^ sw2)];
                afr[i][0] = packh2(f00.x, f00.y);
                afr[i][1] = packh2(f10.x, f10.y);
                afr[i][2] = packh2(f01.x, f01.y);
                afr[i][3] = packh2(f11.x, f11.y);
            }
#pragma unroll
            for (int j = 0; j < 8; j++) {
                int n = wn * 64 + j * 8 + (lane >> 2);
                const __half* brow = bs + n * 16;
                int g0 = (0 ^ (n & 1)) << 3;
                int g1 = (1 ^ (n & 1)) << 3;
                bfr[j][0] = *(const uint32_t*)&brow[g0 + c];
                bfr[j][1] = *(const uint32_t*)&brow[g1 + c];
            }
#pragma unroll
            for (int i = 0; i < 2; i++)
#pragma unroll
                for (int j = 0; j < 8; j++)
                    mma_f16(acc[i][j], afr[i], bfr[j]);
        }

        // ---- store epilogue (fp16 outputs) ----
#pragma unroll
        for (int i = 0; i < 2; i++) {
            int r = row0 + wm * 32 + i * 16 + (lane >> 2);
#pragma unroll
            for (int j = 0; j < 8; j++) {
                int col = wn * 64 + j * 8 + (lane & 3) * 2;
                float c0 = __ldg(cvec + col), c1 = __ldg(cvec + col + 1);
                __half* dstm;
                int cc;
                bool isA = (col < 128);
                if (isA) { dstm = Ca; cc = col; }
                else     { dstm = Cb; cc = col - 128; }
                if (r < M) {
                    float s = isA ? __ldg(rowscale + r) : 1.f;
                    *(__half2*)(dstm + (size_t)r * 128 + cc) =
                        __floats2half2_rn((acc[i][j][0] + c0) * s, (acc[i][j][1] + c1) * s);
                }
                if (r + 8 < M) {
                    float s = isA ? __ldg(rowscale + r + 8) : 1.f;
                    *(__half2*)(dstm + (size_t)(r + 8) * 128 + cc) =
                        __floats2half2_rn((acc[i][j][2] + c0) * s, (acc[i][j][3] + c1) * s);
                }
            }
        }

        // ---- fused el/er from fp32 accumulators (wn >= 2) ----
        if (wn >= 2) {
            const int hmask = (H == 4) ? 1 : 0;
            float pel[4][2], per_[4][2];
#pragma unroll
            for (int rr = 0; rr < 4; rr++) { pel[rr][0] = pel[rr][1] = 0.f; per_[rr][0] = per_[rr][1] = 0.f; }
#pragma unroll
            for (int i = 0; i < 2; i++)
#pragma unroll
                for (int j = 0; j < 8; j++) {
                    int col = wn * 64 + j * 8 + (lane & 3) * 2;
                    int cf = col - 128;
                    float a0 = __ldg(alv + cf), a1 = __ldg(alv + cf + 1);
                    float b0 = __ldg(arv + cf), b1 = __ldg(arv + cf + 1);
                    float c0 = __ldg(cvec + col), c1 = __ldg(cvec + col + 1);
                    int hg = (j >> 2) & hmask;
                    float f0 = acc[i][j][0] + c0, f1 = acc[i][j][1] + c1;
                    float f2 = acc[i][j][2] + c0, f3 = acc[i][j][3] + c1;
                    pel[i * 2 + 0][hg] += f0 * a0 + f1 * a1;
                    per_[i * 2 + 0][hg] += f0 * b0 + f1 * b1;
                    pel[i * 2 + 1][hg] += f2 * a0 + f3 * a1;
                    per_[i * 2 + 1][hg] += f2 * b0 + f3 * b1;
                }
#pragma unroll
            for (int rr = 0; rr < 4; rr++)
#pragma unroll
                for (int hg = 0; hg < 2; hg++) {
                    float v = pel[rr][hg];
                    v += __shfl_xor_sync(0xffffffffu, v, 1);
                    v += __shfl_xor_sync(0xffffffffu, v, 2);
                    pel[rr][hg] = v;
                    float w = per_[rr][hg];
                    w += __shfl_xor_sync(0xffffffffu, w, 1);
                    w += __shfl_xor_sync(0xffffffffu, w, 2);
                    per_[rr][hg] = w;
                }
            if ((lane & 3) == 0) {
#pragma unroll
                for (int rr = 0; rr < 4; rr++) {
                    int row = row0 + wm * 32 + (rr >> 1) * 16 + (lane >> 2) + (rr & 1) * 8;
                    if (row < M) {
                        if (H == 4) {
                            // unique writer per (row, head): plain store
#pragma unroll
                            for (int hg = 0; hg < 2; hg++) {
                                int h = (wn - 2) * 2 + hg;
                                el[(size_t)row * 4 + h] = pel[rr][hg];
                                er[(size_t)row * 4 + h] = per_[rr][hg];
                            }
                        } else {
                            atomicAdd(&el[row], pel[rr][0]);
                            atomicAdd(&er[row], per_[rr][0]);
                        }
                    }
                }
            }
        }
    }
}

// ===================================================================
// Fused layer: per-warp softmax prologue + FROZEN gather structure
// ===================================================================
template<int H, int DO_LEAKY, int DO_ATT>
__global__ __launch_bounds__(128) void layer_fused(
    const __half* __restrict__ xw, const __half* __restrict__ f,
    const float* __restrict__ el, const float* __restrict__ er,
    const float* __restrict__ isi,
    const int* __restrict__ rpi, const int* __restrict__ degi, const int* __restrict__ ci,
    const int* __restrict__ rpc, const int* __restrict__ degc, const int* __restrict__ ccol,
    const float* __restrict__ bgc, const float* __restrict__ bga,
    float* __restrict__ z, float* __restrict__ bnsum, float* __restrict__ bnsq,
    float* __restrict__ att)
{
    const int ch = threadIdx.x;
    const int lane = ch & 31;
    const int wid = ch >> 5;
    const int hh = (H == 1) ? 0 : wid;
    const float bc = __ldg(bgc + ch) + __ldg(bga + ch);
    float ls = 0.f, lq = 0.f;

    for (int n = blockIdx.x; n < NN; n += gridDim.x) {
        float a = 0.f;
        int j = __ldg(rpi + n);
        int bend = j + __ldg(degi + n);
        for (; j + 4 <= bend; j += 4) {
            int s0 = __ldg(ci + j), s1 = __ldg(ci + j + 1);
            int s2 = __ldg(ci + j + 2), s3 = __ldg(ci + j + 3);
            float v0 = __half2float(__ldg(xw + (size_t)s0 * 128 + ch));
            float v1 = __half2float(__ldg(xw + (size_t)s1 * 128 + ch));
            float v2 = __half2float(__ldg(xw + (size_t)s2 * 128 + ch));
            float v3 = __half2float(__ldg(xw + (size_t)s3 * 128 + ch));
            a += (v0 + v1) + (v2 + v3);
        }
        for (; j < bend; j++)
            a += __half2float(__ldg(xw + (size_t)__ldg(ci + j) * 128 + ch));

        float g = 0.f;
        int c0 = __ldg(rpc + n), deg = __ldg(degc + n);
        if (deg > 0) {
            float ern = __ldg(er + (size_t)n * H + hh);
            if (deg <= 32) {
                int sn = 0;
                float e = -1e30f;
                bool valid = (lane < deg);
                if (valid) {
                    sn = __ldg(ccol + c0 + lane);
                    e = leakyr(__ldg(el + (size_t)sn * H + hh) + ern);
                }
                float m = e;
#pragma unroll
                for (int off = 16; off; off >>= 1)
                    m = fmaxf(m, __shfl_xor_sync(0xffffffffu, m, off));
                float ex = valid ? __expf(e - m) : 0.f;
                float s = ex;
#pragma unroll
                for (int off = 16; off; off >>= 1)
                    s += __shfl_xor_sync(0xffffffffu, s, off);
                float aj = ex / s;
                if (DO_ATT && wid == 0 && valid) atomicAdd(&att[sn], aj);
                int kk = 0;
                for (; kk + 4 <= deg; kk += 4) {
                    int s0 = __shfl_sync(0xffffffffu, sn, kk);
                    int s1 = __shfl_sync(0xffffffffu, sn, kk + 1);
                    int s2 = __shfl_sync(0xffffffffu, sn, kk + 2);
                    int s3 = __shfl_sync(0xffffffffu, sn, kk + 3);
                    float a0 = __shfl_sync(0xffffffffu, aj, kk);
                    float a1 = __shfl_sync(0xffffffffu, aj, kk + 1);
                    float a2 = __shfl_sync(0xffffffffu, aj, kk + 2);
                    float a3 = __shfl_sync(0xffffffffu, aj, kk + 3);
                    float v0 = __half2float(__ldg(f + (size_t)s0 * 128 + ch));
                    float v1 = __half2float(__ldg(f + (size_t)s1 * 128 + ch));
                    float v2 = __half2float(__ldg(f + (size_t)s2 * 128 + ch));
                    float v3 = __half2float(__ldg(f + (size_t)s3 * 128 + ch));
                    g += a0 * v0 + a1 * v1 + a2 * v2 + a3 * v3;
                }
                for (; kk < deg; kk++) {
                    int s0 = __shfl_sync(0xffffffffu, sn, kk);
                    float a0 = __shfl_sync(0xffffffffu, aj, kk);
                    g += a0 * __half2float(__ldg(f + (size_t)s0 * 128 + ch));
                }
            } else {
                int cend = c0 + deg;
                float m = -1e30f, s = 0.f;
                for (int jj = c0 + lane; jj < cend; jj += 32) {
                    int sn = __ldg(ccol + jj);
                    float e = leakyr(__ldg(el + (size_t)sn * H + hh) + ern);
                    if (e > m) { s *= __expf(m - e); m = e; }
                    s += __expf(e - m);
                }
#pragma unroll
                for (int off = 16; off; off >>= 1) {
                    float mo = __shfl_xor_sync(0xffffffffu, m, off);
                    float so = __shfl_xor_sync(0xffffffffu, s, off);
                    float mm = fmaxf(m, mo);
                    s = s * __expf(m - mm) + so * __expf(mo - mm);
                    m = mm;
                }
                float inv = 1.f / s;
                for (int j0 = c0; j0 < cend; j0 += 32) {
                    int cnt = min(32, cend - j0);
                    int sn = 0;
                    float aj = 0.f;
                    if (lane < cnt) {
                        sn = __ldg(ccol + j0 + lane);
                        float e = leakyr(__ldg(el + (size_t)sn * H + hh) + ern);
                        aj = __expf(e - m) * inv;
                        if (DO_ATT && wid == 0) atomicAdd(&att[sn], aj);
                    }
                    for (int kk = 0; kk < cnt; kk++) {
                        int s0 = __shfl_sync(0xffffffffu, sn, kk);
                        float a0 = __shfl_sync(0xffffffffu, aj, kk);
                        g += a0 * __half2float(__ldg(f + (size_t)s0 * 128 + ch));
                    }
                }
            }
        }

        float v = a * __ldg(isi + n) + g + bc;
        if (DO_LEAKY) v = leakyr(v);
        z[(size_t)n * 128 + ch] = v;
        ls += v;
        lq += v * v;
    }
    atomicAdd(&bnsum[ch], ls);
    atomicAdd(&bnsq[ch], lq);
}

// -------- pooling: sorted-gid segment accumulation + inline BN --------
__global__ __launch_bounds__(128) void pool_sorted(
    const float* __restrict__ z,
    const float* __restrict__ bnsum, const float* __restrict__ bnsq,
    const float* __restrict__ gam, const float* __restrict__ bet,
    const float* __restrict__ att,
    const int* __restrict__ gid, float* gsum)
{
    const int ch = threadIdx.x;
    int n0 = blockIdx.x * 128;
    int n1 = min(n0 + 128, NN);
    if (n0 >= NN) return;
    float mu = __ldg(bnsum + ch) / (float)NN;
    float var = __ldg(bnsq + ch) / (float)NN - mu * mu;
    float sc = __ldg(gam + ch) * rsqrtf(var + 1e-5f);
    float sh = __ldg(bet + ch) - mu * sc;

    int cur = __ldg(gid + n0);
    float acc = 0.f;
    for (int n = n0; n < n1; n++) {
        int gg = __ldg(gid + n);
        if (gg != cur) {
            atomicAdd(&gsum[cur * 128 + ch], acc);
            acc = 0.f;
            cur = gg;
        }
        float v = z[(size_t)n * 128 + ch] * sc + sh;
        acc += v * __ldg(att + n);
    }
    atomicAdd(&gsum[cur * 128 + ch], acc);
}
__global__ void out_kernel(const float* __restrict__ gsum, const float* __restrict__ gcnt,
                           const float* __restrict__ att, float* __restrict__ out)
{
    int i = blockIdx.x * blockDim.x + threadIdx.x;
    if (i < GN * 128) {
        out[i] = gsum[i] / fmaxf(gcnt[i >> 7], 1.f);
    } else if (i < GN * 128 + NN) {
        out[i] = att[i - GN * 128];
    }
}

static inline int cdiv(int a, int b) { return (a + b - 1) / b; }

extern "C" void kernel_launch(void* const* d_in, const int* in_sizes, int n_in,
                              void* d_out, int out_size)
{
    (void)in_sizes; (void)n_in; (void)out_size;
    const float* feat = (const float*)d_in[0];
    const int* isrc = (const int*)d_in[1];
    const int* idst = (const int*)d_in[2];
    const int* csrc = (const int*)d_in[3];
    const int* cdst = (const int*)d_in[4];
    const int* gid  = (const int*)d_in[5];
    const float* Wgc[3]  = {(const float*)d_in[6],  (const float*)d_in[12], (const float*)d_in[18]};
    const float* bgc[3]  = {(const float*)d_in[7],  (const float*)d_in[13], (const float*)d_in[19]};
    const float* Wgat[3] = {(const float*)d_in[8],  (const float*)d_in[14], (const float*)d_in[20]};
    const float* al[3]   = {(const float*)d_in[9],  (const float*)d_in[15], (const float*)d_in[21]};
    const float* ar[3]   = {(const float*)d_in[10], (const float*)d_in[16], (const float*)d_in[22]};
    const float* bga[3]  = {(const float*)d_in[11], (const float*)d_in[17], (const float*)d_in[23]};
    const float* gam[3]  = {(const float*)d_in[24], (const float*)d_in[26], (const float*)d_in[28]};
    const float* bet[3]  = {(const float*)d_in[25], (const float*)d_in[27], (const float*)d_in[29]};
    float* out = (float*)d_out;

    __half *xw, *f, *wp;
    float *z, *el, *er, *cvec;
    float *iso, *isi, *att, *gsum, *gcnt, *bnsum, *bnsq;
    int *idegi, *idegc, *rpi, *rpc, *curi, *curc, *bsum, *ci, *ccol;
    cudaGetSymbolAddress((void**)&xw, g_xw);
    cudaGetSymbolAddress((void**)&f, g_f);
    cudaGetSymbolAddress((void**)&z, g_z);
    cudaGetSymbolAddress((void**)&el, g_el);
    cudaGetSymbolAddress((void**)&er, g_er);
    cudaGetSymbolAddress((void**)&wp, g_wp);
    cudaGetSymbolAddress((void**)&cvec, g_cvec);
    cudaGetSymbolAddress((void**)&iso, g_iso);
    cudaGetSymbolAddress((void**)&isi, g_isi);
    cudaGetSymbolAddress((void**)&att, g_att);
    cudaGetSymbolAddress((void**)&gsum, g_gsum);
    cudaGetSymbolAddress((void**)&gcnt, g_gcnt);
    cudaGetSymbolAddress((void**)&bnsum, g_bnsum);
    cudaGetSymbolAddress((void**)&bnsq, g_bnsq);
    cudaGetSymbolAddress((void**)&idegi, g_idegi);
    cudaGetSymbolAddress((void**)&idegc, g_idegc);
    cudaGetSymbolAddress((void**)&rpi, g_rpi);
    cudaGetSymbolAddress((void**)&rpc, g_rpc);
    cudaGetSymbolAddress((void**)&curi, g_curi);
    cudaGetSymbolAddress((void**)&curc, g_curc);
    cudaGetSymbolAddress((void**)&bsum, g_bsum);
    cudaGetSymbolAddress((void**)&ci, g_ci);
    cudaGetSymbolAddress((void**)&ccol, g_ccol);

    int nsm = 148;
    cudaDeviceGetAttribute(&nsm, cudaDevAttrMultiProcessorCount, 0);
    if (nsm < 1) nsm = 148;
    const int NB = cdiv(NN, 256);
    const int ZB = cdiv(NN * 4, 256);
    const int NT = cdiv(NN, 128);

    prep_all<<<FDIM + 256 + ZB, 256>>>(Wgc[0], Wgat[0], nullptr, nullptr,
                                       nullptr, nullptr, 0, FDIM, wp, cvec,
                                       el, er, bnsum, bnsq,
                                       1, iso, idegi, idegc, att, gsum, gcnt);
    edge_deg<<<cdiv(EIN + ECN + NN, 256), 256>>>(isrc, idst, cdst, gid, iso, idegi, idegc, gcnt);
    scan1dual<<<NB, 256>>>(idegi, idegc, rpi, rpc, bsum, iso, isi, NN);
    scan23dual<<<NB, 256>>>(rpi, rpc, bsum, curi, curc, NN, NB);
    scatter_dual<<<cdiv(EIN + ECN, 256), 256>>>(isrc, idst, csrc, cdst, curi, curc, ci, ccol);

    const int Hs[3] = {4, 4, 1};
    for (int L = 0; L < 3; L++) {
        int K = (L == 0) ? FDIM : CC;
        int H = Hs[L];
        int cur = (L & 1) * CC;
        int prev = ((L + 1) & 1) * CC;

        if (L > 0)
            prep_all<<<K + 256 + ZB, 256>>>(Wgc[L], Wgat[L], gam[L - 1], bet[L - 1],
                                            bnsum + prev, bnsq + prev, 1, K, wp, cvec,
                                            el, er, bnsum + cur, bnsq + cur,
                                            0, nullptr, nullptr, nullptr, nullptr,
                                            nullptr, nullptr);

        gemm_dual_async<<<nsm, 512>>>((L == 0) ? feat : z, wp, cvec, xw, f,
                                      iso, al[L], ar[L], el, er, NN, K, H, NT);

        if (L < 2)
            layer_fused<4, 1, 0><<<2048, 128>>>(xw, f, el, er, isi, rpi, idegi, ci,
                                                rpc, idegc, ccol, bgc[L], bga[L],
                                                z, bnsum + cur, bnsq + cur, att);
        else
            layer_fused<1, 0, 1><<<2048, 128>>>(xw, f, el, er, isi, rpi, idegi, ci,
                                                rpc, idegc, ccol, bgc[L], bga[L],
                                                z, bnsum + cur, bnsq + cur, att);
    }

    pool_sorted<<<cdiv(NN, 128), 128>>>(z, bnsum, bnsq, gam[2], bet[2], att, gid, gsum);
    out_kernel<<<cdiv(GN * CC + NN, 256), 256>>>(gsum, gcnt, att, out);
}